// round 15
// baseline (speedup 1.0000x reference)
#include <cuda_runtime.h>
#include <cuda_bf16.h>
#include <stdint.h>

#define NPT  64
#define NC   500000
#define NANG 2016
#define G    8            // Givens passes per group in build_M
#define NT   128          // fp32 columns per gemm tile
#define KPW  36           // padded k-words (32 + 4) per n-row in SMEM

// M split to bf16: A[m][k] = mus[m] * M[m][k] = hi + lo
__device__ __nv_bfloat16 g_Mhi[NPT * NPT];
__device__ __nv_bfloat16 g_Mlo[NPT * NPT];

// ---------------------------------------------------------------------------
// Kernel 1: composite rotation matrix via blocked 8-pass cascade.
// Reassociated: out = fmaf(cs.x, w, cs.y*vt) puts only ONE 4-cyc fma on the
// w-cascade per stage (the mul hangs off vt, which is off-chain).
// ---------------------------------------------------------------------------
__global__ void __launch_bounds__(64) build_M_kernel(const float* __restrict__ angles,
                                                     const float* __restrict__ mus) {
    __shared__ float2 scs[NANG];
    __shared__ float  sm[NPT + 1][NPT];
    const int t = threadIdx.x;

    for (int a = t; a < NANG; a += 64) {
        float s, c;
        sincosf(angles[a], &s, &c);
        scs[a] = make_float2(c, s);
    }
#pragma unroll
    for (int i = 0; i < NPT; ++i) sm[i][t] = (i == t) ? 1.0f : 0.0f;
    sm[NPT][t] = 0.0f;
    __syncthreads();

    for (int g = 0; g < NPT / G; ++g) {
        const int b = g * G;
        int aj[G];
#pragma unroll
        for (int j = 0; j < G; ++j) {
            const int it = b + j;
            aj[j] = 63 * it - (it * (it - 1)) / 2 - it - 1;
        }

        float vt[G];
        vt[0] = sm[b][t];

        // peel rows b+1 .. b+G-1 (stage-entry edges)
#pragma unroll
        for (int rr = 1; rr < G; ++rr) {
            const int r = b + rr;
            float w = sm[r][t];
#pragma unroll
            for (int j = 0; j < G; ++j) {
                if (j < rr) {
                    const float2 cs = scs[aj[j] + r];
                    const float out = fmaf(cs.x, w, cs.y * vt[j]);
                    vt[j] = fmaf(-cs.y, w, cs.x * vt[j]);
                    w = out;
                } else if (j == rr) {
                    vt[j] = w;
                }
            }
        }

        // main rows: all 8 stages active
        if (b + G < NPT) {
            float w = sm[b + G][t];
            for (int r = b + G; r < NPT; ++r) {
                const float wn = sm[r + 1][t];
#pragma unroll
                for (int j = 0; j < G; ++j) {
                    const float2 cs = scs[aj[j] + r];
                    const float out = fmaf(cs.x, w, cs.y * vt[j]);   // w-chain: 1 fma
                    vt[j] = fmaf(-cs.y, w, cs.x * vt[j]);
                    w = out;
                }
                sm[r][t] = w;
                w = wn;
            }
        }

#pragma unroll
        for (int j = 0; j < G; ++j) sm[b + j][t] = vt[j];
    }

    // A[m][k]: m = i (row), k = t (this thread's column). Split to bf16 hi/lo.
    for (int i = 0; i < NPT; ++i) {
        const float v = sm[i][t] * __ldg(&mus[i]);
        const __nv_bfloat16 h = __float2bfloat16(v);
        g_Mhi[i * NPT + t] = h;
        g_Mlo[i * NPT + t] = __float2bfloat16(v - __bfloat162float(h));
    }
}

// ---------------------------------------------------------------------------
// HMMA m16n8k16 bf16 wrapper
// ---------------------------------------------------------------------------
__device__ __forceinline__ void mma16816(float* c, const uint32_t* a, uint32_t b0, uint32_t b1) {
    asm volatile(
        "mma.sync.aligned.m16n8k16.row.col.f32.bf16.bf16.f32 "
        "{%0,%1,%2,%3}, {%4,%5,%6,%7}, {%8,%9}, {%0,%1,%2,%3};"
        : "+f"(c[0]), "+f"(c[1]), "+f"(c[2]), "+f"(c[3])
        : "r"(a[0]), "r"(a[1]), "r"(a[2]), "r"(a[3]), "r"(b0), "r"(b1));
}

// ---------------------------------------------------------------------------
// Kernel 2: Y = A @ X via 3-term bf16 split (A_hi@X_hi + A_hi@X_lo + A_lo@X_hi).
// 256 threads, tile = 64k x 128n.
//   Warp layout: wm = (wid&3) -> M rows [wm*16, +16); wn = wid>>2 -> cols [wn*64, +64).
//   SMEM B layout: [n][k-word], word = (bf16 k even, bf16 k odd), KPW=36 pad
//   -> MMA-phase B loads are bank-conflict-free (bank = 4n + t + 8ks).
// ---------------------------------------------------------------------------
__global__ void __launch_bounds__(256, 2) gemm_kernel(const float* __restrict__ X,
                                                      float* __restrict__ Y) {
    __shared__ uint32_t shi[NT][KPW];   // 18.4 KB
    __shared__ uint32_t slo[NT][KPW];   // 18.4 KB

    const int tid  = threadIdx.x;
    const int lane = tid & 31;
    const int wid  = tid >> 5;
    const int gid  = lane >> 2;
    const int tig  = lane & 3;
    const int wm   = wid & 3;
    const int wn   = wid >> 2;

    // ---- A fragments (both splits) from global; L2-resident, broadcast
    uint32_t ahi[4][4], alo[4][4];
    {
        const int m0 = wm * 16 + gid;
        const int m1 = m0 + 8;
#pragma unroll
        for (int ks = 0; ks < 4; ++ks) {
            const int k0 = ks * 16 + tig * 2;
            ahi[ks][0] = *(const uint32_t*)&g_Mhi[m0 * NPT + k0];
            ahi[ks][1] = *(const uint32_t*)&g_Mhi[m1 * NPT + k0];
            ahi[ks][2] = *(const uint32_t*)&g_Mhi[m0 * NPT + k0 + 8];
            ahi[ks][3] = *(const uint32_t*)&g_Mhi[m1 * NPT + k0 + 8];
            alo[ks][0] = *(const uint32_t*)&g_Mlo[m0 * NPT + k0];
            alo[ks][1] = *(const uint32_t*)&g_Mlo[m1 * NPT + k0];
            alo[ks][2] = *(const uint32_t*)&g_Mlo[m0 * NPT + k0 + 8];
            alo[ks][3] = *(const uint32_t*)&g_Mlo[m1 * NPT + k0 + 8];
        }
    }

    // ---- load X tile + convert to bf16 hi/lo, store [n][kword]
    const long cb = (long)blockIdx.x * NT;
    {
        const int cn = (tid & 31) | (((tid >> 5) & 3) << 5);  // 0..127: this thread's column
        const int kh = tid >> 7;                              // 0/1: k half (32 rows)
        const long col = cb + cn;
        const bool ok = (col < NC);
        const float* xp = X + (long)(kh * 32) * NC + (ok ? col : 0);
#pragma unroll
        for (int i = 0; i < 16; ++i) {
            float v0 = 0.f, v1 = 0.f;
            if (ok) {
                v0 = xp[(long)(2 * i) * NC];
                v1 = xp[(long)(2 * i + 1) * NC];
            }
            __nv_bfloat162 h = __floats2bfloat162_rn(v0, v1);   // .x low = k even
            const float2 hf = __bfloat1622float2(h);
            __nv_bfloat162 l = __floats2bfloat162_rn(v0 - hf.x, v1 - hf.y);
            shi[cn][kh * 16 + i] = *(uint32_t*)&h;
            slo[cn][kh * 16 + i] = *(uint32_t*)&l;
        }
    }
    __syncthreads();

    // ---- MMAs: 8 n-frags x 4 k-steps x 3 products
    float acc[8][4];
#pragma unroll
    for (int f = 0; f < 8; ++f)
#pragma unroll
        for (int r = 0; r < 4; ++r) acc[f][r] = 0.f;

#pragma unroll
    for (int f = 0; f < 8; ++f) {
        const int n = wn * 64 + f * 8 + gid;
#pragma unroll
        for (int ks = 0; ks < 4; ++ks) {
            const uint32_t bh0 = shi[n][8 * ks + tig];
            const uint32_t bh1 = shi[n][8 * ks + tig + 4];
            const uint32_t bl0 = slo[n][8 * ks + tig];
            const uint32_t bl1 = slo[n][8 * ks + tig + 4];
            mma16816(acc[f], ahi[ks], bh0, bh1);
            mma16816(acc[f], ahi[ks], bl0, bl1);
            mma16816(acc[f], alo[ks], bh0, bh1);
        }
    }

    // ---- epilogue: c0=[gid][2t], c1=[gid][2t+1], c2=[gid+8][2t], c3=[gid+8][2t+1]
    {
        const int m0 = wm * 16 + gid;
        const int m1 = m0 + 8;
#pragma unroll
        for (int f = 0; f < 8; ++f) {
            const long col = cb + wn * 64 + f * 8 + tig * 2;
            if (col < NC) {
                *(float2*)&Y[(long)m0 * NC + col] = make_float2(acc[f][0], acc[f][1]);
                *(float2*)&Y[(long)m1 * NC + col] = make_float2(acc[f][2], acc[f][3]);
            }
        }
    }
}

// ---------------------------------------------------------------------------
extern "C" void kernel_launch(void* const* d_in, const int* in_sizes, int n_in,
                              void* d_out, int out_size) {
    const float* X      = (const float*)d_in[0];
    const float* angles = (const float*)d_in[1];
    const float* mus    = (const float*)d_in[2];
    float* Y = (float*)d_out;

    build_M_kernel<<<1, 64>>>(angles, mus);

    const int grid = (NC + NT - 1) / NT;   // 3907
    gemm_kernel<<<grid, 256>>>(X, Y);
}